// round 15
// baseline (speedup 1.0000x reference)
#include <cuda_runtime.h>
#include <cstdint>

// Haar 3D, stride-2, 2x2x2 depthwise, 8 filters per channel.
// x: [N=2, C=16, D=128, H=128, W=128] fp32
// y: [N=2, C*8=128, D2=64, H2=64, W2=64] fp32
//
// One CTA per (n,c,d2) slab; PREFETCH-DISTANCE-4 register pipeline over h2
// (16 outstanding LDGs/warp steady-state). DRAM% has risen monotonically with
// pipeline depth (77.5 / 79.0 / 79.7 / 81.1 for depth 0/1/2/3); achieved occ
// (31.7%) is far below the residency cap even at ~96 regs, so deeper
// prefetch is free until the per-warp LDG queue (M_max~55) or RF binds.

#define C_IN   16
#define D_IN   128
#define H_IN   128
#define W_IN   128
#define D2     64
#define H2     64
#define W2     64

struct Quad { float4 a00, a01, a10, a11; };

__device__ __forceinline__ Quad load_quad(const float* __restrict__ xin)
{
    Quad q;
    q.a00 = __ldcs(reinterpret_cast<const float4*>(xin));
    q.a01 = __ldcs(reinterpret_cast<const float4*>(xin + W_IN));
    q.a10 = __ldcs(reinterpret_cast<const float4*>(xin + H_IN * W_IN));
    q.a11 = __ldcs(reinterpret_cast<const float4*>(xin + H_IN * W_IN + W_IN));
    return q;
}

__global__ __launch_bounds__(256) void haar3d_kernel(
    const float* __restrict__ x, float* __restrict__ y)
{
    const int w4  = threadIdx.x;        // 0..31: 2 w-blocks (4 floats)
    const int ty  = threadIdx.y;        // 0..7
    const int ncd = blockIdx.x;         // (n*C + c)*64 + d2
    const int d2  = ncd & 63;
    const int nc  = ncd >> 6;

    const float* xin0 = x
        + ((size_t)nc * D_IN + 2 * d2) * (size_t)(H_IN * W_IN)
        + 4 * w4;

    const size_t plane = (size_t)D2 * H2 * W2;   // 262144
    float* yo0 = y + (size_t)nc * 8 * plane
                   + (size_t)d2 * (H2 * W2)
                   + 2 * w4;

    // Row address for pipeline stage k: h2 = ty + 8*k  -> byte row 2*h2
    #define ROW_PTR(k) (xin0 + (size_t)(2 * (ty + 8 * (k))) * W_IN)

    // Prologue: fill pipeline (k=0..3 in flight)
    Quad b0 = load_quad(ROW_PTR(0));
    Quad b1 = load_quad(ROW_PTR(1));
    Quad b2 = load_quad(ROW_PTR(2));
    Quad b3 = load_quad(ROW_PTR(3));

    #pragma unroll
    for (int k = 0; k < 8; k++) {
        // Prefetch k+4 before consuming b0 (loads span four compute phases)
        Quad b4;
        if (k < 4) b4 = load_quad(ROW_PTR(k + 4));

        const float4 c00 = b0.a00, c01 = b0.a01, c10 = b0.a10, c11 = b0.a11;

        // ---- Block 0 (w pair .x,.y) ----
        float t0_00 = c00.x + c00.y, t1_00 = c00.x - c00.y;
        float t0_01 = c01.x + c01.y, t1_01 = c01.x - c01.y;
        float t0_10 = c10.x + c10.y, t1_10 = c10.x - c10.y;
        float t0_11 = c11.x + c11.y, t1_11 = c11.x - c11.y;
        float u00_0 = t0_00 + t0_01, u10_0 = t0_00 - t0_01;
        float u01_0 = t1_00 + t1_01, u11_0 = t1_00 - t1_01;
        float u00_1 = t0_10 + t0_11, u10_1 = t0_10 - t0_11;
        float u01_1 = t1_10 + t1_11, u11_1 = t1_10 - t1_11;
        float o0_b0 = (u00_0 + u00_1) * 0.125f;
        float o1_b0 = (u01_0 + u01_1) * 0.125f;
        float o2_b0 = (u10_0 + u10_1) * 0.125f;
        float o3_b0 = (u11_0 + u11_1) * 0.125f;
        float o4_b0 = (u00_0 - u00_1) * 0.125f;
        float o5_b0 = (u01_0 - u01_1) * 0.125f;
        float o6_b0 = (u10_0 - u10_1) * 0.125f;
        float o7_b0 = (u11_0 - u11_1) * 0.125f;

        // ---- Block 1 (w pair .z,.w) ----
        t0_00 = c00.z + c00.w; t1_00 = c00.z - c00.w;
        t0_01 = c01.z + c01.w; t1_01 = c01.z - c01.w;
        t0_10 = c10.z + c10.w; t1_10 = c10.z - c10.w;
        t0_11 = c11.z + c11.w; t1_11 = c11.z - c11.w;
        u00_0 = t0_00 + t0_01; u10_0 = t0_00 - t0_01;
        u01_0 = t1_00 + t1_01; u11_0 = t1_00 - t1_01;
        u00_1 = t0_10 + t0_11; u10_1 = t0_10 - t0_11;
        u01_1 = t1_10 + t1_11; u11_1 = t1_10 - t1_11;
        float o0_b1 = (u00_0 + u00_1) * 0.125f;
        float o1_b1 = (u01_0 + u01_1) * 0.125f;
        float o2_b1 = (u10_0 + u10_1) * 0.125f;
        float o3_b1 = (u11_0 + u11_1) * 0.125f;
        float o4_b1 = (u00_0 - u00_1) * 0.125f;
        float o5_b1 = (u01_0 - u01_1) * 0.125f;
        float o6_b1 = (u10_0 - u10_1) * 0.125f;
        float o7_b1 = (u11_0 - u11_1) * 0.125f;

        float* yo = yo0 + (size_t)(ty + 8 * k) * W2;
        __stcs(reinterpret_cast<float2*>(yo + 0 * plane), make_float2(o0_b0, o0_b1));
        __stcs(reinterpret_cast<float2*>(yo + 1 * plane), make_float2(o1_b0, o1_b1));
        __stcs(reinterpret_cast<float2*>(yo + 2 * plane), make_float2(o2_b0, o2_b1));
        __stcs(reinterpret_cast<float2*>(yo + 3 * plane), make_float2(o3_b0, o3_b1));
        __stcs(reinterpret_cast<float2*>(yo + 4 * plane), make_float2(o4_b0, o4_b1));
        __stcs(reinterpret_cast<float2*>(yo + 5 * plane), make_float2(o5_b0, o5_b1));
        __stcs(reinterpret_cast<float2*>(yo + 6 * plane), make_float2(o6_b0, o6_b1));
        __stcs(reinterpret_cast<float2*>(yo + 7 * plane), make_float2(o7_b0, o7_b1));

        // Rotate pipeline
        b0 = b1;
        b1 = b2;
        b2 = b3;
        b3 = b4;
    }
    #undef ROW_PTR
}

extern "C" void kernel_launch(void* const* d_in, const int* in_sizes, int n_in,
                              void* d_out, int out_size)
{
    const float* x = (const float*)d_in[0];
    // d_in[1] is the fixed Haar filter bank; its values (+-0.125 products) are
    // hardcoded in the butterfly above.
    float* y = (float*)d_out;

    // One CTA per (n, c, d2) slab: grid = 2*16*64 = 2048, block = 32x8.
    dim3 block(32, 8, 1);
    dim3 grid(2 * C_IN * D2, 1, 1);
    haar3d_kernel<<<grid, block>>>(x, y);
}